// round 2
// baseline (speedup 1.0000x reference)
#include <cuda_runtime.h>
#include <cstdint>

#define NN 50000
#define DD 128
#define EE 800000

// ---------------- scratch (static device globals: no allocation) ----------------
__device__ __align__(16) float g_h[NN * DD];     // features between layers
__device__ __align__(16) float g_agg[NN * DD];   // scatter-add accumulator
__device__ __align__(16) float g_y1[NN * DD];    // GEMM1 output (pre-BN)
__device__ __align__(16) float g_y2[NN * DD];    // GEMM2 output (pre-BN)
__device__ __align__(16) float g_stats[512];     // sum1, sq1, sum2, sq2
__device__ __align__(16) float g_s[DD];          // BN scale
__device__ __align__(16) float g_t[DD];          // BN shift
__device__ int g_is64;                           // edge_index dtype flag

// ---------------- detect edge_index dtype (int32 vs int64) ----------------
// If the buffer is int64 with values < 2^31 (node ids < 50000), every odd
// 32-bit word is 0. Genuine random int32 ids: odds of 8 zeros ~ (1/50000)^8.
__global__ void detect_k(const int* __restrict__ ei32) {
    int is64 = 1;
#pragma unroll
    for (int i = 0; i < 8; i++)
        if (ei32[2 * i + 1] != 0) is64 = 0;
    g_is64 = is64;
}

// ---------------- zero agg + stats ----------------
__global__ void zero_k() {
    int i = blockIdx.x * 256 + threadIdx.x;     // 6250 * 256 = NN*DD/4 exactly
    ((float4*)g_agg)[i] = make_float4(0.f, 0.f, 0.f, 0.f);
    if (i < 512) g_stats[i] = 0.f;
}

// ---------------- gather relu(h[src]) + scatter-add to agg[dst] ----------------
// one warp per edge, each thread handles 4 floats; vector red.add (sm_90+)
__global__ void scatter_k(const float* __restrict__ h, const int* __restrict__ ei32) {
    long long t = (long long)blockIdx.x * 256 + threadIdx.x;
    int e = (int)(t >> 5);
    if (e >= EE) return;
    int c = ((int)t & 31) * 4;
    int s, d;
    if (g_is64) {
        s = ei32[2 * e];                // low word of int64
        d = ei32[2 * (EE + e)];
    } else {
        s = ei32[e];
        d = ei32[EE + e];
    }
    float4 v = *(const float4*)(h + (size_t)s * DD + c);
    v.x = fmaxf(v.x, 0.f); v.y = fmaxf(v.y, 0.f);
    v.z = fmaxf(v.z, 0.f); v.w = fmaxf(v.w, 0.f);
    float* p = g_agg + (size_t)d * DD + c;
    asm volatile("red.global.add.v4.f32 [%0], {%1,%2,%3,%4};"
                 :: "l"(p), "f"(v.x), "f"(v.y), "f"(v.z), "f"(v.w) : "memory");
}

// ---------------- GEMM (128x128 tile, K=128) with fused prologue + BN-stats epilogue ----
// MODE 1: A = (1+eps[l])*h + agg          (GIN combine)   -> Y = A@W1 + b1, accumulate stats
// MODE 2: A = relu(y1*g_s + g_t)          (BN1 + ReLU)    -> Y = A@W2 + b2, accumulate stats
template <int MODE>
__global__ void __launch_bounds__(256, 2) gemm_bn_k(
    const float* __restrict__ A0,
    const float* __restrict__ epsp, int layer,
    const float* __restrict__ W, const float* __restrict__ bias,
    float* __restrict__ Y, float* __restrict__ colsum, float* __restrict__ colsq)
{
    __shared__ __align__(16) float As[128][36];   // [m][k], padded
    __shared__ __align__(16) float Bs[32][132];   // [k][n], padded
    __shared__ float csum[128], csq[128];

    int tid = threadIdx.x;
    int tx = tid & 15, ty = tid >> 4;
    int rowBase = blockIdx.x * 128;

    float acc[8][8];
#pragma unroll
    for (int i = 0; i < 8; i++)
#pragma unroll
        for (int j = 0; j < 8; j++) acc[i][j] = 0.f;

    float epsv = (MODE == 1) ? (1.0f + epsp[layer]) : 0.0f;

    for (int k0 = 0; k0 < 128; k0 += 32) {
        // A tile load: 128 rows x 32 cols, fused prologue
        int c = (tid & 7) * 4;
        int mb = tid >> 3;
#pragma unroll
        for (int i = 0; i < 4; i++) {
            int m = mb + 32 * i;
            int gr = rowBase + m;
            float4 v = make_float4(0.f, 0.f, 0.f, 0.f);
            if (gr < NN) {
                v = *(const float4*)(A0 + (size_t)gr * DD + k0 + c);
                if (MODE == 1) {
                    float4 a2 = *(const float4*)(g_agg + (size_t)gr * DD + k0 + c);
                    v.x = fmaf(epsv, v.x, a2.x);
                    v.y = fmaf(epsv, v.y, a2.y);
                    v.z = fmaf(epsv, v.z, a2.z);
                    v.w = fmaf(epsv, v.w, a2.w);
                } else {
                    float4 sv = *(const float4*)(g_s + k0 + c);
                    float4 tv = *(const float4*)(g_t + k0 + c);
                    v.x = fmaxf(fmaf(v.x, sv.x, tv.x), 0.f);
                    v.y = fmaxf(fmaf(v.y, sv.y, tv.y), 0.f);
                    v.z = fmaxf(fmaf(v.z, sv.z, tv.z), 0.f);
                    v.w = fmaxf(fmaf(v.w, sv.w, tv.w), 0.f);
                }
            }
            *(float4*)&As[m][c] = v;
        }
        // B tile load: 32 x 128 of W
#pragma unroll
        for (int i = 0; i < 4; i++) {
            int idx = tid + 256 * i;
            int kk = idx >> 5;
            int n4 = (idx & 31) * 4;
            *(float4*)&Bs[kk][n4] = *(const float4*)(W + (size_t)(k0 + kk) * DD + n4);
        }
        __syncthreads();

#pragma unroll 8
        for (int kk = 0; kk < 32; kk++) {
            float a[8];
#pragma unroll
            for (int i = 0; i < 8; i++) a[i] = As[ty * 8 + i][kk];
            float4 b0 = *(float4*)&Bs[kk][tx * 8];
            float4 b1 = *(float4*)&Bs[kk][tx * 8 + 4];
            float b[8] = {b0.x, b0.y, b0.z, b0.w, b1.x, b1.y, b1.z, b1.w};
#pragma unroll
            for (int i = 0; i < 8; i++)
#pragma unroll
                for (int j = 0; j < 8; j++)
                    acc[i][j] = fmaf(a[i], b[j], acc[i][j]);
        }
        __syncthreads();
    }

    // ---- epilogue: bias add, store Y, fused BN statistics ----
    float bj[8];
#pragma unroll
    for (int j = 0; j < 8; j++) bj[j] = bias[tx * 8 + j];

    if (tid < 128) { csum[tid] = 0.f; csq[tid] = 0.f; }
    __syncthreads();

    float psum[8], psq[8];
#pragma unroll
    for (int j = 0; j < 8; j++) { psum[j] = 0.f; psq[j] = 0.f; }

#pragma unroll
    for (int i = 0; i < 8; i++) {
        int gr = rowBase + ty * 8 + i;
        if (gr < NN) {
            float v[8];
#pragma unroll
            for (int j = 0; j < 8; j++) {
                v[j] = acc[i][j] + bj[j];
                psum[j] += v[j];
                psq[j]  += v[j] * v[j];
            }
            *(float4*)(Y + (size_t)gr * DD + tx * 8)     = make_float4(v[0], v[1], v[2], v[3]);
            *(float4*)(Y + (size_t)gr * DD + tx * 8 + 4) = make_float4(v[4], v[5], v[6], v[7]);
        }
    }
#pragma unroll
    for (int j = 0; j < 8; j++) {
        atomicAdd(&csum[tx * 8 + j], psum[j]);
        atomicAdd(&csq[tx * 8 + j],  psq[j]);
    }
    __syncthreads();
    if (tid < 128) {
        atomicAdd(&colsum[tid], csum[tid]);
        atomicAdd(&colsq[tid],  csq[tid]);
    }
}

// ---------------- BN stats finalize: scale/shift from sums ----------------
__global__ void bn_stats_k(const float* __restrict__ cs, const float* __restrict__ cq,
                           const float* __restrict__ g, const float* __restrict__ b)
{
    int d = threadIdx.x;
    float mu  = cs[d] * (1.0f / NN);
    float var = cq[d] * (1.0f / NN) - mu * mu;
    float sc  = g[d] * rsqrtf(var + 1e-5f);
    g_s[d] = sc;
    g_t[d] = b[d] - mu * sc;
}

// ---------------- apply outer BN (+ optional ReLU), write layer output ----------------
__global__ void finalize_k(float* __restrict__ out, int relu_flag) {
    int i = blockIdx.x * 256 + threadIdx.x;   // 6250 * 256 = NN*DD/4
    int d4 = (i * 4) & 127;
    float4 v = ((const float4*)g_y2)[i];
    float4 s = *(const float4*)(g_s + d4);
    float4 t = *(const float4*)(g_t + d4);
    v.x = fmaf(v.x, s.x, t.x);
    v.y = fmaf(v.y, s.y, t.y);
    v.z = fmaf(v.z, s.z, t.z);
    v.w = fmaf(v.w, s.w, t.w);
    if (relu_flag) {
        v.x = fmaxf(v.x, 0.f); v.y = fmaxf(v.y, 0.f);
        v.z = fmaxf(v.z, 0.f); v.w = fmaxf(v.w, 0.f);
    }
    ((float4*)out)[i] = v;
}

extern "C" void kernel_launch(void* const* d_in, const int* in_sizes, int n_in,
                              void* d_out, int out_size)
{
    const float* x    = (const float*)d_in[0];
    const int*   ei32 = (const int*)d_in[1];    // int32 OR int64 (decoded on device)
    const float* eps  = (const float*)d_in[2];
    const float* W1   = (const float*)d_in[3];
    const float* b1   = (const float*)d_in[4];
    const float* bn1g = (const float*)d_in[5];
    const float* bn1b = (const float*)d_in[6];
    const float* W2   = (const float*)d_in[7];
    const float* b2   = (const float*)d_in[8];
    const float* bn2g = (const float*)d_in[9];
    const float* bn2b = (const float*)d_in[10];

    // If the buffer has 2*EE elements it is int32; int64 would report the same
    // element count, so decode layout from the data itself (detect_k).
    float *hbuf, *y1p, *y2p, *statsp;
    cudaGetSymbolAddress((void**)&hbuf,   g_h);
    cudaGetSymbolAddress((void**)&y1p,    g_y1);
    cudaGetSymbolAddress((void**)&y2p,    g_y2);
    cudaGetSymbolAddress((void**)&statsp, g_stats);

    const int gemmBlocks = (NN + 127) / 128;   // 391

    detect_k<<<1, 1>>>(ei32);

    const float* hin = x;
    for (int l = 0; l < 3; l++) {
        zero_k<<<6250, 256>>>();
        scatter_k<<<100000, 256>>>(hin, ei32);
        gemm_bn_k<1><<<gemmBlocks, 256>>>(hin, eps, l,
                                          W1 + (size_t)l * DD * DD, b1 + (size_t)l * DD,
                                          y1p, statsp, statsp + 128);
        bn_stats_k<<<1, 128>>>(statsp, statsp + 128, bn1g + (size_t)l * DD, bn1b + (size_t)l * DD);
        gemm_bn_k<2><<<gemmBlocks, 256>>>(y1p, eps, l,
                                          W2 + (size_t)l * DD * DD, b2 + (size_t)l * DD,
                                          y2p, statsp + 256, statsp + 384);
        bn_stats_k<<<1, 128>>>(statsp + 256, statsp + 384, bn2g + (size_t)l * DD, bn2b + (size_t)l * DD);
        float* hout = (l == 2) ? (float*)d_out : hbuf;
        finalize_k<<<6250, 256>>>(hout, (l < 2) ? 1 : 0);
        hin = hbuf;
    }
}

// round 4
// speedup vs baseline: 1.4309x; 1.4309x over previous
#include <cuda_runtime.h>
#include <cuda_bf16.h>
#include <cstdint>

#define NN 50000
#define DD 128
#define EE 800000

// ---------------- scratch (static device globals: no allocation) ----------------
__device__ __align__(16) float g_h[NN * DD];
__device__ __align__(16) float g_agg[NN * DD];
__device__ __align__(16) float g_y1[NN * DD];
__device__ __align__(16) float g_y2[NN * DD];
__device__ __align__(16) float g_stats[512];   // sum1, sq1, sum2, sq2
__device__ __align__(16) float g_s[DD];
__device__ __align__(16) float g_t[DD];
__device__ int g_is64;
// bf16 weight images, W^T as [N][K] row-major: 6 matrices (W1[0..2], W2[0..2]), hi+lo split
__device__ __align__(16) unsigned short g_whi[6 * DD * DD];
__device__ __align__(16) unsigned short g_wlo[6 * DD * DD];

__device__ __forceinline__ uint32_t smem_to_u32(const void* p) {
    uint32_t a;
    asm("{ .reg .u64 t; cvta.to.shared.u64 t, %1; cvt.u32.u64 %0, t; }" : "=r"(a) : "l"(p));
    return a;
}

#define LDMX4(r0, r1, r2, r3, addr) \
    asm volatile("ldmatrix.sync.aligned.m8n8.x4.shared.b16 {%0,%1,%2,%3}, [%4];" \
                 : "=r"(r0), "=r"(r1), "=r"(r2), "=r"(r3) : "r"(addr))

#define MMA16816(d, a, b) \
    asm volatile("mma.sync.aligned.m16n8k16.row.col.f32.bf16.bf16.f32 " \
                 "{%0,%1,%2,%3}, {%4,%5,%6,%7}, {%8,%9}, {%0,%1,%2,%3};" \
                 : "+f"((d)[0]), "+f"((d)[1]), "+f"((d)[2]), "+f"((d)[3]) \
                 : "r"((a)[0]), "r"((a)[1]), "r"((a)[2]), "r"((a)[3]), "r"((b)[0]), "r"((b)[1]))

// ---------------- detect edge_index dtype (int32 vs int64) ----------------
__global__ void detect_k(const int* __restrict__ ei32) {
    int is64 = 1;
#pragma unroll
    for (int i = 0; i < 8; i++)
        if (ei32[2 * i + 1] != 0) is64 = 0;
    g_is64 = is64;
}

// ---------------- weight prep: transpose to [N][K] + bf16 hi/lo split ----------------
__global__ void wprep_k(const float* __restrict__ W1, const float* __restrict__ W2) {
    int b = blockIdx.x;                      // 384 blocks
    int wi = b >> 6;                         // 0..5
    int id = ((b & 63) << 8) + threadIdx.x;  // 0..16383
    const float* W = (wi < 3) ? (W1 + (size_t)wi * 16384) : (W2 + (size_t)(wi - 3) * 16384);
    int k = id >> 7, n = id & 127;
    float v = W[k * 128 + n];
    __nv_bfloat16 hb = __float2bfloat16(v);
    __nv_bfloat16 lb = __float2bfloat16(v - __bfloat162float(hb));
    g_whi[(size_t)wi * 16384 + n * 128 + k] = __bfloat16_as_ushort(hb);
    g_wlo[(size_t)wi * 16384 + n * 128 + k] = __bfloat16_as_ushort(lb);
}

// ---------------- zero agg + stats ----------------
__global__ void zero_k() {
    int i = blockIdx.x * 256 + threadIdx.x;  // 6250 * 256 = NN*DD/4
    ((float4*)g_agg)[i] = make_float4(0.f, 0.f, 0.f, 0.f);
    if (i < 512) g_stats[i] = 0.f;
}

// ---------------- gather relu(h[src]) + scatter-add via red.v4 ----------------
__global__ void scatter_k(const float* __restrict__ h, const int* __restrict__ ei32) {
    long long t = (long long)blockIdx.x * 256 + threadIdx.x;
    int e = (int)(t >> 5);
    if (e >= EE) return;
    int c = ((int)t & 31) * 4;
    int s, d;
    if (g_is64) { s = ei32[2 * e]; d = ei32[2 * (EE + e)]; }
    else        { s = ei32[e];     d = ei32[EE + e]; }
    float4 v = *(const float4*)(h + (size_t)s * DD + c);
    v.x = fmaxf(v.x, 0.f); v.y = fmaxf(v.y, 0.f);
    v.z = fmaxf(v.z, 0.f); v.w = fmaxf(v.w, 0.f);
    float* p = g_agg + (size_t)d * DD + c;
    asm volatile("red.global.add.v4.f32 [%0], {%1,%2,%3,%4};"
                 :: "l"(p), "f"(v.x), "f"(v.y), "f"(v.z), "f"(v.w) : "memory");
}

// ---------------- HMMA GEMM (128x128x128 tile, bf16-split, 3 products) ----------------
// MODE 1: A = (1+eps[l])*h + agg ;  MODE 2: A = relu(y1*g_s + g_t)
// Y = A @ W + bias (fp32 accum)
// SMEM tiles: padded row-major bf16, stride 136 elems (272B) -> conflict-free ldmatrix.
#define TSTRIDE 136                       // bf16 elems per row
#define TBYTES  (128 * TSTRIDE * 2)       // 34816 per tile
#define BIAS_OFF 0
#define AHI_OFF  1024
#define ALO_OFF  (AHI_OFF + TBYTES)
#define BHI_OFF  (ALO_OFF + TBYTES)
#define BLO_OFF  (BHI_OFF + TBYTES)
#define GEMM_SMEM (BLO_OFF + TBYTES)      // 140288 bytes

template <int MODE>
__global__ void __launch_bounds__(256, 1) gemm_tc_k(
    const float* __restrict__ A0, const float* __restrict__ epsp, int layer,
    const unsigned short* __restrict__ whi, const unsigned short* __restrict__ wlo,
    const float* __restrict__ bias, float* __restrict__ Y)
{
    extern __shared__ __align__(16) char smem[];
    uint32_t sb = smem_to_u32(smem);
    int tid = threadIdx.x;
    int wid = tid >> 5, lane = tid & 31;
    int rowBase = blockIdx.x * 128;

    if (tid < 128) *(float*)(smem + BIAS_OFF + tid * 4) = bias[tid];

    // ---- B tiles: copy hi/lo [N][K] images into padded smem rows ----
    {
        const uint4* sh = (const uint4*)whi;
        const uint4* sl = (const uint4*)wlo;
#pragma unroll
        for (int i = 0; i < 8; i++) {
            int id = i * 256 + tid;          // 2048 x 16B chunks
            int r = id >> 4, c16 = id & 15;
            uint32_t dst = (uint32_t)(r * (TSTRIDE * 2) + c16 * 16);
            *(uint4*)(smem + BHI_OFF + dst) = sh[id];
            *(uint4*)(smem + BLO_OFF + dst) = sl[id];
        }
    }

    // ---- A tile: fused transform + bf16 split + padded store ----
    float epsv = (MODE == 1) ? (1.0f + epsp[layer]) : 0.0f;
#pragma unroll
    for (int it = 0; it < 8; it++) {
        int id = it * 256 + tid;            // 2048 groups of 8 elems
        int row = id >> 4;
        int col = (id & 15) * 8;
        int gr = rowBase + row;
        float v[8];
#pragma unroll
        for (int j = 0; j < 8; j++) v[j] = 0.f;
        if (gr < NN) {
            float4 p0 = *(const float4*)(A0 + (size_t)gr * DD + col);
            float4 p1 = *(const float4*)(A0 + (size_t)gr * DD + col + 4);
            v[0] = p0.x; v[1] = p0.y; v[2] = p0.z; v[3] = p0.w;
            v[4] = p1.x; v[5] = p1.y; v[6] = p1.z; v[7] = p1.w;
            if (MODE == 1) {
                float4 a0 = *(const float4*)(g_agg + (size_t)gr * DD + col);
                float4 a1 = *(const float4*)(g_agg + (size_t)gr * DD + col + 4);
                v[0] = fmaf(epsv, v[0], a0.x); v[1] = fmaf(epsv, v[1], a0.y);
                v[2] = fmaf(epsv, v[2], a0.z); v[3] = fmaf(epsv, v[3], a0.w);
                v[4] = fmaf(epsv, v[4], a1.x); v[5] = fmaf(epsv, v[5], a1.y);
                v[6] = fmaf(epsv, v[6], a1.z); v[7] = fmaf(epsv, v[7], a1.w);
            } else {
#pragma unroll
                for (int j = 0; j < 8; j++)
                    v[j] = fmaxf(fmaf(v[j], g_s[col + j], g_t[col + j]), 0.f);
            }
        }
        uint32_t h[4], l[4];
#pragma unroll
        for (int j = 0; j < 4; j++) {
            __nv_bfloat16 h0 = __float2bfloat16(v[2 * j]);
            __nv_bfloat16 h1 = __float2bfloat16(v[2 * j + 1]);
            __nv_bfloat16 l0 = __float2bfloat16(v[2 * j] - __bfloat162float(h0));
            __nv_bfloat16 l1 = __float2bfloat16(v[2 * j + 1] - __bfloat162float(h1));
            h[j] = ((uint32_t)__bfloat16_as_ushort(h1) << 16) | __bfloat16_as_ushort(h0);
            l[j] = ((uint32_t)__bfloat16_as_ushort(l1) << 16) | __bfloat16_as_ushort(l0);
        }
        uint32_t off = (uint32_t)(row * (TSTRIDE * 2) + col * 2);
        *(uint4*)(smem + AHI_OFF + off) = make_uint4(h[0], h[1], h[2], h[3]);
        *(uint4*)(smem + ALO_OFF + off) = make_uint4(l[0], l[1], l[2], l[3]);
    }
    __syncthreads();

    // ---- warp MMA mainloop: warp (wm, wn) owns 64x32; 4x4 m16n8k16 atoms ----
    int wm = wid & 1, wn = wid >> 1;
    int m0 = wm * 64, n0 = wn * 32;

    float acc[4][4][4];
#pragma unroll
    for (int i = 0; i < 4; i++)
#pragma unroll
        for (int j = 0; j < 4; j++)
#pragma unroll
            for (int q = 0; q < 4; q++) acc[i][j][q] = 0.f;

    // ldmatrix per-lane address components (byte offsets within tile)
    // A x4 frag (m16,k16): lanes 0-15 rows m0+l, k+0 ; lanes 16-31 rows, k+8
    uint32_t aOff = (uint32_t)((m0 + (lane & 15)) * (TSTRIDE * 2) + (lane >> 4) * 16);
    // B x4 frag (k16,n16): rows n0 + (l&7) + (l>>4)*8 ; col k + ((l>>3)&1)*8
    uint32_t bOff = (uint32_t)((n0 + (lane & 7) + (lane >> 4) * 8) * (TSTRIDE * 2) + ((lane >> 3) & 1) * 16);

#pragma unroll
    for (int ks = 0; ks < 8; ks++) {
        uint32_t kByte = (uint32_t)(ks * 32);   // k0 * 2 bytes
        uint32_t ah[4][4], al[4][4], bh[4][2], bl[4][2];
#pragma unroll
        for (int i = 0; i < 4; i++) {
            uint32_t ad = sb + AHI_OFF + aOff + kByte + (uint32_t)(i * 16 * TSTRIDE * 2);
            LDMX4(ah[i][0], ah[i][1], ah[i][2], ah[i][3], ad);
        }
#pragma unroll
        for (int i = 0; i < 4; i++) {
            uint32_t ad = sb + ALO_OFF + aOff + kByte + (uint32_t)(i * 16 * TSTRIDE * 2);
            LDMX4(al[i][0], al[i][1], al[i][2], al[i][3], ad);
        }
#pragma unroll
        for (int jj = 0; jj < 2; jj++) {
            uint32_t bd = sb + BHI_OFF + bOff + kByte + (uint32_t)(jj * 16 * TSTRIDE * 2);
            uint32_t r0, r1, r2, r3;
            LDMX4(r0, r1, r2, r3, bd);
            bh[2 * jj][0] = r0; bh[2 * jj][1] = r1;
            bh[2 * jj + 1][0] = r2; bh[2 * jj + 1][1] = r3;
            bd = sb + BLO_OFF + bOff + kByte + (uint32_t)(jj * 16 * TSTRIDE * 2);
            LDMX4(r0, r1, r2, r3, bd);
            bl[2 * jj][0] = r0; bl[2 * jj][1] = r1;
            bl[2 * jj + 1][0] = r2; bl[2 * jj + 1][1] = r3;
        }
#pragma unroll
        for (int i = 0; i < 4; i++)
#pragma unroll
            for (int j = 0; j < 4; j++) MMA16816(acc[i][j], ah[i], bh[j]);
#pragma unroll
        for (int i = 0; i < 4; i++)
#pragma unroll
            for (int j = 0; j < 4; j++) MMA16816(acc[i][j], ah[i], bl[j]);
#pragma unroll
        for (int i = 0; i < 4; i++)
#pragma unroll
            for (int j = 0; j < 4; j++) MMA16816(acc[i][j], al[i], bh[j]);
    }

    // ---- epilogue: bias add + store ----
    int rq = lane >> 2, cq = (lane & 3) * 2;
    const float* bs = (const float*)(smem + BIAS_OFF);
#pragma unroll
    for (int i = 0; i < 4; i++) {
        int r0g = rowBase + m0 + i * 16 + rq;
#pragma unroll
        for (int j = 0; j < 4; j++) {
            int cg = n0 + j * 8 + cq;
            float bx = bs[cg], by = bs[cg + 1];
            if (r0g < NN)
                *(float2*)(Y + (size_t)r0g * DD + cg) =
                    make_float2(acc[i][j][0] + bx, acc[i][j][1] + by);
            if (r0g + 8 < NN)
                *(float2*)(Y + (size_t)(r0g + 8) * DD + cg) =
                    make_float2(acc[i][j][2] + bx, acc[i][j][3] + by);
        }
    }
}

// ---------------- column stats: sum & sumsq over rows ----------------
__global__ void stats_k(const float* __restrict__ Y, float* __restrict__ cs, float* __restrict__ cq) {
    __shared__ float ps[256], pq[256];
    int tid = threadIdx.x;
    int c = tid & 127, half = tid >> 7;
    int r0 = blockIdx.x * 250;           // 200 blocks * 250 rows
    float s = 0.f, q = 0.f;
    for (int r = r0 + half; r < r0 + 250; r += 2) {
        float v = Y[(size_t)r * DD + c];
        s += v;
        q += v * v;
    }
    ps[tid] = s; pq[tid] = q;
    __syncthreads();
    if (tid < 128) {
        atomicAdd(&cs[tid], ps[tid] + ps[tid + 128]);
        atomicAdd(&cq[tid], pq[tid] + pq[tid + 128]);
    }
}

// ---------------- BN scale/shift ----------------
__global__ void bn_stats_k(const float* __restrict__ cs, const float* __restrict__ cq,
                           const float* __restrict__ g, const float* __restrict__ b)
{
    int d = threadIdx.x;
    float mu  = cs[d] * (1.0f / NN);
    float var = cq[d] * (1.0f / NN) - mu * mu;
    float sc  = g[d] * rsqrtf(var + 1e-5f);
    g_s[d] = sc;
    g_t[d] = b[d] - mu * sc;
}

// ---------------- apply outer BN (+ optional ReLU) ----------------
__global__ void finalize_k(float* __restrict__ out, int relu_flag) {
    int i = blockIdx.x * 256 + threadIdx.x;
    int d4 = (i * 4) & 127;
    float4 v = ((const float4*)g_y2)[i];
    float4 s = *(const float4*)(g_s + d4);
    float4 t = *(const float4*)(g_t + d4);
    v.x = fmaf(v.x, s.x, t.x);
    v.y = fmaf(v.y, s.y, t.y);
    v.z = fmaf(v.z, s.z, t.z);
    v.w = fmaf(v.w, s.w, t.w);
    if (relu_flag) {
        v.x = fmaxf(v.x, 0.f); v.y = fmaxf(v.y, 0.f);
        v.z = fmaxf(v.z, 0.f); v.w = fmaxf(v.w, 0.f);
    }
    ((float4*)out)[i] = v;
}

extern "C" void kernel_launch(void* const* d_in, const int* in_sizes, int n_in,
                              void* d_out, int out_size)
{
    const float* x    = (const float*)d_in[0];
    const int*   ei32 = (const int*)d_in[1];
    const float* eps  = (const float*)d_in[2];
    const float* W1   = (const float*)d_in[3];
    const float* b1   = (const float*)d_in[4];
    const float* bn1g = (const float*)d_in[5];
    const float* bn1b = (const float*)d_in[6];
    const float* W2   = (const float*)d_in[7];
    const float* b2   = (const float*)d_in[8];
    const float* bn2g = (const float*)d_in[9];
    const float* bn2b = (const float*)d_in[10];

    float *hbuf, *y1p, *y2p, *statsp;
    unsigned short *whip, *wlop;
    cudaGetSymbolAddress((void**)&hbuf,   g_h);
    cudaGetSymbolAddress((void**)&y1p,    g_y1);
    cudaGetSymbolAddress((void**)&y2p,    g_y2);
    cudaGetSymbolAddress((void**)&statsp, g_stats);
    cudaGetSymbolAddress((void**)&whip,   g_whi);
    cudaGetSymbolAddress((void**)&wlop,   g_wlo);

    cudaFuncSetAttribute(gemm_tc_k<1>, cudaFuncAttributeMaxDynamicSharedMemorySize, GEMM_SMEM);
    cudaFuncSetAttribute(gemm_tc_k<2>, cudaFuncAttributeMaxDynamicSharedMemorySize, GEMM_SMEM);

    const int gemmBlocks = (NN + 127) / 128;   // 391

    detect_k<<<1, 1>>>(ei32);
    wprep_k<<<384, 256>>>(W1, W2);

    const float* hin = x;
    for (int l = 0; l < 3; l++) {
        zero_k<<<6250, 256>>>();
        scatter_k<<<100000, 256>>>(hin, ei32);
        gemm_tc_k<1><<<gemmBlocks, 256, GEMM_SMEM>>>(hin, eps, l,
            whip + (size_t)l * 16384, wlop + (size_t)l * 16384,
            b1 + (size_t)l * DD, y1p);
        stats_k<<<200, 256>>>(y1p, statsp, statsp + 128);
        bn_stats_k<<<1, 128>>>(statsp, statsp + 128, bn1g + (size_t)l * DD, bn1b + (size_t)l * DD);
        gemm_tc_k<2><<<gemmBlocks, 256, GEMM_SMEM>>>(y1p, eps, l,
            whip + (size_t)(3 + l) * 16384, wlop + (size_t)(3 + l) * 16384,
            b2 + (size_t)l * DD, y2p);
        stats_k<<<200, 256>>>(y2p, statsp + 256, statsp + 384);
        bn_stats_k<<<1, 128>>>(statsp + 256, statsp + 384, bn2g + (size_t)l * DD, bn2b + (size_t)l * DD);
        float* hout = (l == 2) ? (float*)d_out : hbuf;
        finalize_k<<<6250, 256>>>(hout, (l < 2) ? 1 : 0);
        hin = hbuf;
    }
}

// round 5
// speedup vs baseline: 2.2603x; 1.5796x over previous
#include <cuda_runtime.h>
#include <cuda_bf16.h>
#include <cstdint>

#define NN 50000
#define DD 128
#define EE 800000

// ---------------- scratch (static device globals: no allocation) ----------------
__device__ __align__(16) float g_h[NN * DD];
__device__ __align__(16) float g_agg[NN * DD];
__device__ __align__(16) float g_y1[NN * DD];
__device__ __align__(16) float g_y2[NN * DD];
__device__ __align__(16) float g_stats[512];   // sum1, sq1, sum2, sq2
__device__ __align__(16) float g_s[DD];
__device__ __align__(16) float g_t[DD];
__device__ int g_is64;
// bf16 weight images, W^T as [N][K] row-major: 6 matrices, hi+lo split
__device__ __align__(16) unsigned short g_whi[6 * DD * DD];
__device__ __align__(16) unsigned short g_wlo[6 * DD * DD];
// CSR (edges bucketed by dst) — built once per launch
__device__ int g_deg[50176];
__device__ int g_scan[50176];
__device__ int g_off[50176];
__device__ int g_cursor[50176];
__device__ int g_bsum[64];
__device__ int g_srcs[EE];

__device__ __forceinline__ uint32_t smem_to_u32(const void* p) {
    uint32_t a;
    asm("{ .reg .u64 t; cvta.to.shared.u64 t, %1; cvt.u32.u64 %0, t; }" : "=r"(a) : "l"(p));
    return a;
}

#define LDMX4(r0, r1, r2, r3, addr) \
    asm volatile("ldmatrix.sync.aligned.m8n8.x4.shared.b16 {%0,%1,%2,%3}, [%4];" \
                 : "=r"(r0), "=r"(r1), "=r"(r2), "=r"(r3) : "r"(addr))

#define MMA16816(d, a, b) \
    asm volatile("mma.sync.aligned.m16n8k16.row.col.f32.bf16.bf16.f32 " \
                 "{%0,%1,%2,%3}, {%4,%5,%6,%7}, {%8,%9}, {%0,%1,%2,%3};" \
                 : "+f"((d)[0]), "+f"((d)[1]), "+f"((d)[2]), "+f"((d)[3]) \
                 : "r"((a)[0]), "r"((a)[1]), "r"((a)[2]), "r"((a)[3]), "r"((b)[0]), "r"((b)[1]))

// ---------------- detect edge_index dtype (int32 vs int64) ----------------
__global__ void detect_k(const int* __restrict__ ei32) {
    int is64 = 1;
#pragma unroll
    for (int i = 0; i < 8; i++)
        if (ei32[2 * i + 1] != 0) is64 = 0;
    g_is64 = is64;
}

// ---------------- weight prep: transpose to [N][K] + bf16 hi/lo split ----------------
__global__ void wprep_k(const float* __restrict__ W1, const float* __restrict__ W2) {
    int b = blockIdx.x;                      // 384 blocks
    int wi = b >> 6;
    int id = ((b & 63) << 8) + threadIdx.x;
    const float* W = (wi < 3) ? (W1 + (size_t)wi * 16384) : (W2 + (size_t)(wi - 3) * 16384);
    int k = id >> 7, n = id & 127;
    float v = W[k * 128 + n];
    __nv_bfloat16 hb = __float2bfloat16(v);
    __nv_bfloat16 lb = __float2bfloat16(v - __bfloat162float(hb));
    g_whi[(size_t)wi * 16384 + n * 128 + k] = __bfloat16_as_ushort(hb);
    g_wlo[(size_t)wi * 16384 + n * 128 + k] = __bfloat16_as_ushort(lb);
}

// ================= CSR build (once; edge_index is loop-invariant) =================
__global__ void zdeg_k() {                  // 196 blocks x 256 = 50176
    g_deg[blockIdx.x * 256 + threadIdx.x] = 0;
}
__global__ void count_k(const int* __restrict__ ei32) {   // 3125 x 256
    int e = blockIdx.x * 256 + threadIdx.x;
    if (e >= EE) return;
    int d = g_is64 ? ei32[2 * (EE + e)] : ei32[EE + e];
    atomicAdd(&g_deg[d], 1);
}
__global__ void scan1_k() {                 // 49 blocks x 1024
    __shared__ int sm[1024];
    int t = threadIdx.x;
    int gid = blockIdx.x * 1024 + t;
    int v = (gid < NN) ? g_deg[gid] : 0;
    sm[t] = v;
    __syncthreads();
    for (int o = 1; o < 1024; o <<= 1) {
        int tv = (t >= o) ? sm[t - o] : 0;
        __syncthreads();
        sm[t] += tv;
        __syncthreads();
    }
    g_scan[gid] = sm[t] - v;                // exclusive within block
    if (t == 1023) g_bsum[blockIdx.x] = sm[1023];
}
__global__ void scan2_k() {                 // 1 thread: exclusive scan of 49 block sums
    int run = 0;
    for (int i = 0; i < 49; i++) { int t = g_bsum[i]; g_bsum[i] = run; run += t; }
}
__global__ void scan3_k() {                 // 49 blocks x 1024
    int gid = blockIdx.x * 1024 + threadIdx.x;
    int o = g_scan[gid] + g_bsum[blockIdx.x];
    g_off[gid] = o;
    g_cursor[gid] = o;
}
__global__ void fill_k(const int* __restrict__ ei32) {    // 3125 x 256
    int e = blockIdx.x * 256 + threadIdx.x;
    if (e >= EE) return;
    int s, d;
    if (g_is64) { s = ei32[2 * e]; d = ei32[2 * (EE + e)]; }
    else        { s = ei32[e];     d = ei32[EE + e]; }
    int pos = atomicAdd(&g_cursor[d], 1);
    g_srcs[pos] = s;
}

// ---------------- aggregation: per-node gather + register sum (no atomics) --------
__global__ void __launch_bounds__(256) agg_k(const float* __restrict__ h) {
    int w = blockIdx.x * 8 + (threadIdx.x >> 5);  // 6250 blocks -> 50000 warps
    int lane = threadIdx.x & 31;
    int s = g_off[w], t = g_off[w + 1];
    float4 acc = make_float4(0.f, 0.f, 0.f, 0.f);
    int e = s;
    for (; e + 1 < t; e += 2) {
        int s0 = g_srcs[e], s1 = g_srcs[e + 1];
        float4 v0 = *(const float4*)(h + (size_t)s0 * DD + lane * 4);
        float4 v1 = *(const float4*)(h + (size_t)s1 * DD + lane * 4);
        acc.x += fmaxf(v0.x, 0.f) + fmaxf(v1.x, 0.f);
        acc.y += fmaxf(v0.y, 0.f) + fmaxf(v1.y, 0.f);
        acc.z += fmaxf(v0.z, 0.f) + fmaxf(v1.z, 0.f);
        acc.w += fmaxf(v0.w, 0.f) + fmaxf(v1.w, 0.f);
    }
    if (e < t) {
        int s0 = g_srcs[e];
        float4 v0 = *(const float4*)(h + (size_t)s0 * DD + lane * 4);
        acc.x += fmaxf(v0.x, 0.f);
        acc.y += fmaxf(v0.y, 0.f);
        acc.z += fmaxf(v0.z, 0.f);
        acc.w += fmaxf(v0.w, 0.f);
    }
    *(float4*)(g_agg + (size_t)w * DD + lane * 4) = acc;
}

// ---------------- zero BN stats (512 floats) ----------------
__global__ void zstats_k() { g_stats[threadIdx.x] = 0.f; }

// ---------------- HMMA GEMM (128x128x128, bf16-split, fused BN-stats epilogue) ----
#define TSTRIDE 136
#define TBYTES  (128 * TSTRIDE * 2)
#define BIAS_OFF 0
#define AHI_OFF  1024
#define ALO_OFF  (AHI_OFF + TBYTES)
#define BHI_OFF  (ALO_OFF + TBYTES)
#define BLO_OFF  (BHI_OFF + TBYTES)
#define STAT_OFF (BLO_OFF + TBYTES)
#define GEMM_SMEM (STAT_OFF + 1024)

template <int MODE>
__global__ void __launch_bounds__(256, 1) gemm_tc_k(
    const float* __restrict__ A0, const float* __restrict__ epsp, int layer,
    const unsigned short* __restrict__ whi, const unsigned short* __restrict__ wlo,
    const float* __restrict__ bias, float* __restrict__ Y,
    float* __restrict__ colsum, float* __restrict__ colsq)
{
    extern __shared__ __align__(16) char smem[];
    uint32_t sb = smem_to_u32(smem);
    int tid = threadIdx.x;
    int wid = tid >> 5, lane = tid & 31;
    int rowBase = blockIdx.x * 128;

    if (tid < 128) *(float*)(smem + BIAS_OFF + tid * 4) = bias[tid];
    ((float*)(smem + STAT_OFF))[tid] = 0.f;   // 256 floats: csum[128], csq[128]

    // ---- B tiles ----
    {
        const uint4* sh = (const uint4*)whi;
        const uint4* sl = (const uint4*)wlo;
#pragma unroll
        for (int i = 0; i < 8; i++) {
            int id = i * 256 + tid;
            int r = id >> 4, c16 = id & 15;
            uint32_t dst = (uint32_t)(r * (TSTRIDE * 2) + c16 * 16);
            *(uint4*)(smem + BHI_OFF + dst) = sh[id];
            *(uint4*)(smem + BLO_OFF + dst) = sl[id];
        }
    }

    // ---- A tile: fused transform + bf16 split ----
    float epsv = (MODE == 1) ? (1.0f + epsp[layer]) : 0.0f;
#pragma unroll
    for (int it = 0; it < 8; it++) {
        int id = it * 256 + tid;
        int row = id >> 4;
        int col = (id & 15) * 8;
        int gr = rowBase + row;
        float v[8];
#pragma unroll
        for (int j = 0; j < 8; j++) v[j] = 0.f;
        if (gr < NN) {
            float4 p0 = *(const float4*)(A0 + (size_t)gr * DD + col);
            float4 p1 = *(const float4*)(A0 + (size_t)gr * DD + col + 4);
            v[0] = p0.x; v[1] = p0.y; v[2] = p0.z; v[3] = p0.w;
            v[4] = p1.x; v[5] = p1.y; v[6] = p1.z; v[7] = p1.w;
            if (MODE == 1) {
                float4 a0 = *(const float4*)(g_agg + (size_t)gr * DD + col);
                float4 a1 = *(const float4*)(g_agg + (size_t)gr * DD + col + 4);
                v[0] = fmaf(epsv, v[0], a0.x); v[1] = fmaf(epsv, v[1], a0.y);
                v[2] = fmaf(epsv, v[2], a0.z); v[3] = fmaf(epsv, v[3], a0.w);
                v[4] = fmaf(epsv, v[4], a1.x); v[5] = fmaf(epsv, v[5], a1.y);
                v[6] = fmaf(epsv, v[6], a1.z); v[7] = fmaf(epsv, v[7], a1.w);
            } else {
#pragma unroll
                for (int j = 0; j < 8; j++)
                    v[j] = fmaxf(fmaf(v[j], g_s[col + j], g_t[col + j]), 0.f);
            }
        }
        uint32_t h[4], l[4];
#pragma unroll
        for (int j = 0; j < 4; j++) {
            __nv_bfloat16 h0 = __float2bfloat16(v[2 * j]);
            __nv_bfloat16 h1 = __float2bfloat16(v[2 * j + 1]);
            __nv_bfloat16 l0 = __float2bfloat16(v[2 * j] - __bfloat162float(h0));
            __nv_bfloat16 l1 = __float2bfloat16(v[2 * j + 1] - __bfloat162float(h1));
            h[j] = ((uint32_t)__bfloat16_as_ushort(h1) << 16) | __bfloat16_as_ushort(h0);
            l[j] = ((uint32_t)__bfloat16_as_ushort(l1) << 16) | __bfloat16_as_ushort(l0);
        }
        uint32_t off = (uint32_t)(row * (TSTRIDE * 2) + col * 2);
        *(uint4*)(smem + AHI_OFF + off) = make_uint4(h[0], h[1], h[2], h[3]);
        *(uint4*)(smem + ALO_OFF + off) = make_uint4(l[0], l[1], l[2], l[3]);
    }
    __syncthreads();

    // ---- warp MMA mainloop ----
    int wm = wid & 1, wn = wid >> 1;
    int m0 = wm * 64, n0 = wn * 32;

    float acc[4][4][4];
#pragma unroll
    for (int i = 0; i < 4; i++)
#pragma unroll
        for (int j = 0; j < 4; j++)
#pragma unroll
            for (int q = 0; q < 4; q++) acc[i][j][q] = 0.f;

    uint32_t aOff = (uint32_t)((m0 + (lane & 15)) * (TSTRIDE * 2) + (lane >> 4) * 16);
    uint32_t bOff = (uint32_t)((n0 + (lane & 7) + (lane >> 4) * 8) * (TSTRIDE * 2) + ((lane >> 3) & 1) * 16);

#pragma unroll
    for (int ks = 0; ks < 8; ks++) {
        uint32_t kByte = (uint32_t)(ks * 32);
        uint32_t ah[4][4], al[4][4], bh[4][2], bl[4][2];
#pragma unroll
        for (int i = 0; i < 4; i++) {
            uint32_t ad = sb + AHI_OFF + aOff + kByte + (uint32_t)(i * 16 * TSTRIDE * 2);
            LDMX4(ah[i][0], ah[i][1], ah[i][2], ah[i][3], ad);
        }
#pragma unroll
        for (int i = 0; i < 4; i++) {
            uint32_t ad = sb + ALO_OFF + aOff + kByte + (uint32_t)(i * 16 * TSTRIDE * 2);
            LDMX4(al[i][0], al[i][1], al[i][2], al[i][3], ad);
        }
#pragma unroll
        for (int jj = 0; jj < 2; jj++) {
            uint32_t bd = sb + BHI_OFF + bOff + kByte + (uint32_t)(jj * 16 * TSTRIDE * 2);
            uint32_t r0, r1, r2, r3;
            LDMX4(r0, r1, r2, r3, bd);
            bh[2 * jj][0] = r0; bh[2 * jj][1] = r1;
            bh[2 * jj + 1][0] = r2; bh[2 * jj + 1][1] = r3;
            bd = sb + BLO_OFF + bOff + kByte + (uint32_t)(jj * 16 * TSTRIDE * 2);
            LDMX4(r0, r1, r2, r3, bd);
            bl[2 * jj][0] = r0; bl[2 * jj][1] = r1;
            bl[2 * jj + 1][0] = r2; bl[2 * jj + 1][1] = r3;
        }
#pragma unroll
        for (int i = 0; i < 4; i++)
#pragma unroll
            for (int j = 0; j < 4; j++) MMA16816(acc[i][j], ah[i], bh[j]);
#pragma unroll
        for (int i = 0; i < 4; i++)
#pragma unroll
            for (int j = 0; j < 4; j++) MMA16816(acc[i][j], ah[i], bl[j]);
#pragma unroll
        for (int i = 0; i < 4; i++)
#pragma unroll
            for (int j = 0; j < 4; j++) MMA16816(acc[i][j], al[i], bh[j]);
    }

    // ---- epilogue: bias, store, fused BN stats ----
    float* scs = (float*)(smem + STAT_OFF);
    float* scq = scs + 128;
    int rq = lane >> 2, cq = (lane & 3) * 2;
    const float* bs = (const float*)(smem + BIAS_OFF);

    float ps[4][2], pq[4][2];
#pragma unroll
    for (int j = 0; j < 4; j++) { ps[j][0] = ps[j][1] = 0.f; pq[j][0] = pq[j][1] = 0.f; }

#pragma unroll
    for (int i = 0; i < 4; i++) {
        int r0g = rowBase + m0 + i * 16 + rq;
#pragma unroll
        for (int j = 0; j < 4; j++) {
            int cg = n0 + j * 8 + cq;
            float bx = bs[cg], by = bs[cg + 1];
            if (r0g < NN) {
                float v0 = acc[i][j][0] + bx, v1 = acc[i][j][1] + by;
                *(float2*)(Y + (size_t)r0g * DD + cg) = make_float2(v0, v1);
                ps[j][0] += v0; pq[j][0] += v0 * v0;
                ps[j][1] += v1; pq[j][1] += v1 * v1;
            }
            if (r0g + 8 < NN) {
                float v2 = acc[i][j][2] + bx, v3 = acc[i][j][3] + by;
                *(float2*)(Y + (size_t)(r0g + 8) * DD + cg) = make_float2(v2, v3);
                ps[j][0] += v2; pq[j][0] += v2 * v2;
                ps[j][1] += v3; pq[j][1] += v3 * v3;
            }
        }
    }
    // warp reduce over the 8 rq groups (lane bits 2,3,4)
#pragma unroll
    for (int j = 0; j < 4; j++)
#pragma unroll
        for (int c = 0; c < 2; c++) {
#pragma unroll
            for (int m = 4; m <= 16; m <<= 1) {
                ps[j][c] += __shfl_xor_sync(0xFFFFFFFFu, ps[j][c], m);
                pq[j][c] += __shfl_xor_sync(0xFFFFFFFFu, pq[j][c], m);
            }
        }
    if (rq == 0) {
#pragma unroll
        for (int j = 0; j < 4; j++)
#pragma unroll
            for (int c = 0; c < 2; c++) {
                atomicAdd(&scs[n0 + j * 8 + cq + c], ps[j][c]);
                atomicAdd(&scq[n0 + j * 8 + cq + c], pq[j][c]);
            }
    }
    __syncthreads();
    if (tid < 128) {
        atomicAdd(&colsum[tid], scs[tid]);
        atomicAdd(&colsq[tid],  scq[tid]);
    }
}

// ---------------- BN scale/shift ----------------
__global__ void bn_stats_k(const float* __restrict__ cs, const float* __restrict__ cq,
                           const float* __restrict__ g, const float* __restrict__ b)
{
    int d = threadIdx.x;
    float mu  = cs[d] * (1.0f / NN);
    float var = cq[d] * (1.0f / NN) - mu * mu;
    float sc  = g[d] * rsqrtf(var + 1e-5f);
    g_s[d] = sc;
    g_t[d] = b[d] - mu * sc;
}

// ---------------- apply outer BN (+ optional ReLU) ----------------
__global__ void finalize_k(float* __restrict__ out, int relu_flag) {
    int i = blockIdx.x * 256 + threadIdx.x;
    int d4 = (i * 4) & 127;
    float4 v = ((const float4*)g_y2)[i];
    float4 s = *(const float4*)(g_s + d4);
    float4 t = *(const float4*)(g_t + d4);
    v.x = fmaf(v.x, s.x, t.x);
    v.y = fmaf(v.y, s.y, t.y);
    v.z = fmaf(v.z, s.z, t.z);
    v.w = fmaf(v.w, s.w, t.w);
    if (relu_flag) {
        v.x = fmaxf(v.x, 0.f); v.y = fmaxf(v.y, 0.f);
        v.z = fmaxf(v.z, 0.f); v.w = fmaxf(v.w, 0.f);
    }
    ((float4*)out)[i] = v;
}

extern "C" void kernel_launch(void* const* d_in, const int* in_sizes, int n_in,
                              void* d_out, int out_size)
{
    const float* x    = (const float*)d_in[0];
    const int*   ei32 = (const int*)d_in[1];
    const float* eps  = (const float*)d_in[2];
    const float* W1   = (const float*)d_in[3];
    const float* b1   = (const float*)d_in[4];
    const float* bn1g = (const float*)d_in[5];
    const float* bn1b = (const float*)d_in[6];
    const float* W2   = (const float*)d_in[7];
    const float* b2   = (const float*)d_in[8];
    const float* bn2g = (const float*)d_in[9];
    const float* bn2b = (const float*)d_in[10];

    float *hbuf, *y1p, *y2p, *statsp;
    unsigned short *whip, *wlop;
    cudaGetSymbolAddress((void**)&hbuf,   g_h);
    cudaGetSymbolAddress((void**)&y1p,    g_y1);
    cudaGetSymbolAddress((void**)&y2p,    g_y2);
    cudaGetSymbolAddress((void**)&statsp, g_stats);
    cudaGetSymbolAddress((void**)&whip,   g_whi);
    cudaGetSymbolAddress((void**)&wlop,   g_wlo);

    cudaFuncSetAttribute(gemm_tc_k<1>, cudaFuncAttributeMaxDynamicSharedMemorySize, GEMM_SMEM);
    cudaFuncSetAttribute(gemm_tc_k<2>, cudaFuncAttributeMaxDynamicSharedMemorySize, GEMM_SMEM);

    const int gemmBlocks = (NN + 127) / 128;   // 391

    // one-time prep: dtype detect, weight images, CSR build
    detect_k<<<1, 1>>>(ei32);
    wprep_k<<<384, 256>>>(W1, W2);
    zdeg_k<<<196, 256>>>();
    count_k<<<3125, 256>>>(ei32);
    scan1_k<<<49, 1024>>>();
    scan2_k<<<1, 1>>>();
    scan3_k<<<49, 1024>>>();
    fill_k<<<3125, 256>>>(ei32);

    const float* hin = x;
    for (int l = 0; l < 3; l++) {
        zstats_k<<<1, 512>>>();
        agg_k<<<6250, 256>>>(hin);
        gemm_tc_k<1><<<gemmBlocks, 256, GEMM_SMEM>>>(hin, eps, l,
            whip + (size_t)l * 16384, wlop + (size_t)l * 16384,
            b1 + (size_t)l * DD, y1p, statsp, statsp + 128);
        bn_stats_k<<<1, 128>>>(statsp, statsp + 128, bn1g + (size_t)l * DD, bn1b + (size_t)l * DD);
        gemm_tc_k<2><<<gemmBlocks, 256, GEMM_SMEM>>>(y1p, eps, l,
            whip + (size_t)(3 + l) * 16384, wlop + (size_t)(3 + l) * 16384,
            b2 + (size_t)l * DD, y2p, statsp + 256, statsp + 384);
        bn_stats_k<<<1, 128>>>(statsp + 256, statsp + 384, bn2g + (size_t)l * DD, bn2b + (size_t)l * DD);
        float* hout = (l == 2) ? (float*)d_out : hbuf;
        finalize_k<<<6250, 256>>>(hout, (l < 2) ? 1 : 0);
        hin = hbuf;
    }
}